// round 1
// baseline (speedup 1.0000x reference)
#include <cuda_runtime.h>
#include <cuda_bf16.h>

#define FULLMASK 0xFFFFFFFFu

// Layout: 4 locations per warp, 8 lanes per location.
// Within an 8-lane group:  t = lane&7,  h = t>>2 (row parity),  q = t&3 (d-quad).
// Lane holds P[r] (r=0..7): pred row i = 2r + h, columns d = 4q..4q+3.
// Reductions: xor 1,2 = over d-quads; xor 4 = over row parity. All stay inside
// the 8-lane group.
__global__ void __launch_bounds__(256) routing_kernel(
    const float* __restrict__ pred,
    const float* __restrict__ b_in,
    const int*   __restrict__ nit,
    float*       __restrict__ out,
    int n_loc, int ohw)
{
    const int lane = threadIdx.x & 31;
    const int t = lane & 7;
    const int h = t >> 2;
    const int q = t & 3;
    const unsigned warp_id = blockIdx.x * (blockDim.x >> 5) + (threadIdx.x >> 5);
    const int g = lane >> 3;                         // location within warp
    if (warp_id * 4u >= (unsigned)n_loc) return;     // warp-uniform guard
    const unsigned loc = warp_id * 4u + g;

    // ---- load pred tile: 8 coalesced LDG.128 rounds (1 KB per location) ----
    const float4* p4 = reinterpret_cast<const float4*>(pred) + (size_t)warp_id * 256;
    float4 P[8];
#pragma unroll
    for (int r = 0; r < 8; ++r)
        P[r] = p4[64 * g + 8 * r + t];

    // ---- load logits b for this location's rows (broadcast across d-group) ----
    float bb[8];
    const float* brow = b_in + (size_t)(loc % (unsigned)ohw) * 16 + h;
#pragma unroll
    for (int r = 0; r < 8; ++r) bb[r] = __ldg(brow + 2 * r);

    const int iters = *nit;
    float o0, o1, o2, o3;

    // one routing pass: softmax(bb over i) -> weighted sum over i -> squash
    auto pass = [&]() {
        // softmax over the 16 i-values (8 local + parity partner via xor 4)
        float m = bb[0];
#pragma unroll
        for (int r = 1; r < 8; ++r) m = fmaxf(m, bb[r]);
        m = fmaxf(m, __shfl_xor_sync(FULLMASK, m, 4));
        float e[8], s = 0.f;
#pragma unroll
        for (int r = 0; r < 8; ++r) { e[r] = __expf(bb[r] - m); s += e[r]; }
        s += __shfl_xor_sync(FULLMASK, s, 4);
        const float inv = __frcp_rn(s);

        // weighted sum over i (partial over local rows, then parity reduce)
        float a0 = 0.f, a1 = 0.f, a2 = 0.f, a3 = 0.f;
#pragma unroll
        for (int r = 0; r < 8; ++r) {
            const float c = e[r] * inv;
            a0 = fmaf(c, P[r].x, a0);
            a1 = fmaf(c, P[r].y, a1);
            a2 = fmaf(c, P[r].z, a2);
            a3 = fmaf(c, P[r].w, a3);
        }
        a0 += __shfl_xor_sync(FULLMASK, a0, 4);
        a1 += __shfl_xor_sync(FULLMASK, a1, 4);
        a2 += __shfl_xor_sync(FULLMASK, a2, 4);
        a3 += __shfl_xor_sync(FULLMASK, a3, 4);

        // squash: sq over all 16 d (4 local + d-group reduce)
        float sq = a0 * a0 + a1 * a1 + a2 * a2 + a3 * a3;
        sq += __shfl_xor_sync(FULLMASK, sq, 1);
        sq += __shfl_xor_sync(FULLMASK, sq, 2);
        const float scale =
            sq * __frcp_rn((1.f + sq) * __fsqrt_rn(sq + 1e-7f));
        o0 = a0 * scale; o1 = a1 * scale; o2 = a2 * scale; o3 = a3 * scale;
    };

    pass();
    for (int it = 0; it < iters; ++it) {
        // agreement: a[i] = <pred_row_i, out>; partial over local d-quad,
        // then reduce over the 4 d-quads (xor 1, xor 2)
#pragma unroll
        for (int r = 0; r < 8; ++r) {
            float pa = P[r].x * o0 + P[r].y * o1 + P[r].z * o2 + P[r].w * o3;
            pa += __shfl_xor_sync(FULLMASK, pa, 1);
            pa += __shfl_xor_sync(FULLMASK, pa, 2);
            bb[r] += pa;
        }
        pass();
    }

    // ---- store: h==0 lanes hold quads q=0..3, contiguous float4 per location
    if (h == 0)
        reinterpret_cast<float4*>(out)[(size_t)loc * 4 + q] =
            make_float4(o0, o1, o2, o3);
}

extern "C" void kernel_launch(void* const* d_in, const int* in_sizes, int n_in,
                              void* d_out, int out_size) {
    const float* pred = (const float*)d_in[0];
    const float* b    = (const float*)d_in[1];
    const int*   nit  = (const int*)d_in[2];
    float* out = (float*)d_out;

    const int n_loc = in_sizes[0] / 256;   // B*O*H*W locations (I*D = 256 each)
    const int ohw   = in_sizes[1] / 16;    // O*H*W (b has no batch dim)

    const int warps  = (n_loc + 3) / 4;    // 4 locations per warp
    const int blocks = (warps + 7) / 8;    // 8 warps per block
    routing_kernel<<<blocks, 256>>>(pred, b, nit, out, n_loc, ohw);
}

// round 2
// speedup vs baseline: 1.1782x; 1.1782x over previous
#include <cuda_runtime.h>
#include <cuda_bf16.h>

#define FULLMASK 0xFFFFFFFFu
#define LOG2E 1.4426950408889634f

using u64 = unsigned long long;

__device__ __forceinline__ u64 fma2(u64 a, u64 b, u64 c) {
    u64 d; asm("fma.rn.f32x2 %0,%1,%2,%3;" : "=l"(d) : "l"(a), "l"(b), "l"(c)); return d;
}
__device__ __forceinline__ u64 mul2(u64 a, u64 b) {
    u64 d; asm("mul.rn.f32x2 %0,%1,%2;" : "=l"(d) : "l"(a), "l"(b)); return d;
}
__device__ __forceinline__ u64 add2(u64 a, u64 b) {
    u64 d; asm("add.rn.f32x2 %0,%1,%2;" : "=l"(d) : "l"(a), "l"(b)); return d;
}
__device__ __forceinline__ u64 bcast2(float v) {
    u64 d; asm("mov.b64 %0,{%1,%1};" : "=l"(d) : "f"(v)); return d;
}
__device__ __forceinline__ float2 unpk(u64 v) {
    float2 r; asm("mov.b64 {%0,%1},%2;" : "=f"(r.x), "=f"(r.y) : "l"(v)); return r;
}
__device__ __forceinline__ float ex2f(float x) {
    float r; asm("ex2.approx.f32 %0,%1;" : "=f"(r) : "f"(x)); return r;
}
__device__ __forceinline__ float rcpf(float x) {
    float r; asm("rcp.approx.f32 %0,%1;" : "=f"(r) : "f"(x)); return r;
}
__device__ __forceinline__ float rsqf(float x) {
    float r; asm("rsqrt.approx.f32 %0,%1;" : "=f"(r) : "f"(x)); return r;
}

union Row { ulonglong2 u; float4 f; };

// Layout: 4 locations per warp, 8 lanes per location.
// t = lane&7, h = t>>2 (row parity), q = t&3 (d-quad).
// Lane holds rows i = 2r+h (r=0..7), columns d = 4q..4q+3.
// Reductions: xor 1,2 over d-quads; xor 4 over row parity.
// b logits are kept in log2-space (pre-scaled by log2(e)); softmax uses raw
// ex2 with NO max subtraction (values bounded, fp32-safe), and the 1/sum is
// deferred and folded into the squash scale.
__global__ void __launch_bounds__(256) routing_kernel(
    const float* __restrict__ pred,
    const float* __restrict__ b_in,
    const int*   __restrict__ nit,
    float*       __restrict__ out,
    int n_loc, int ohw)
{
    const int lane = threadIdx.x & 31;
    const int t = lane & 7;
    const int h = t >> 2;
    const int q = t & 3;
    const unsigned warp_id = blockIdx.x * (blockDim.x >> 5) + (threadIdx.x >> 5);
    const int g = lane >> 3;
    if (warp_id * 4u >= (unsigned)n_loc) return;
    const unsigned loc = warp_id * 4u + g;

    // ---- pred tile: 8 coalesced LDG.128 rounds ----
    const ulonglong2* p4 =
        reinterpret_cast<const ulonglong2*>(pred) + (size_t)warp_id * 256;
    Row P[8];
#pragma unroll
    for (int r = 0; r < 8; ++r)
        P[r].u = p4[64 * g + 8 * r + t];

    // ---- logits (log2-space) ----
    float bb[8];
    const float* brow = b_in + (size_t)(loc % (unsigned)ohw) * 16 + h;
#pragma unroll
    for (int r = 0; r < 8; ++r) bb[r] = __ldg(brow + 2 * r) * LOG2E;

    const int iters = *nit;
    u64 o01, o23;           // squashed output (d-quad), packed f32x2
    float o0, o1, o2, o3;   // scalar view for agreement dots

    auto pass = [&]() {
        // exp (base-2, no max subtraction) + sum over 16 i
        float e[8];
#pragma unroll
        for (int r = 0; r < 8; ++r) e[r] = ex2f(bb[r]);
        float s = ((e[0] + e[1]) + (e[2] + e[3])) +
                  ((e[4] + e[5]) + (e[6] + e[7]));
        s += __shfl_xor_sync(FULLMASK, s, 4);
        const float inv = rcpf(s);

        // un-normalized weighted sum over i, packed f32x2
        u64 a01 = 0ull, a23 = 0ull;
#pragma unroll
        for (int r = 0; r < 8; ++r) {
            const u64 ee = bcast2(e[r]);
            a01 = fma2(ee, P[r].u.x, a01);
            a23 = fma2(ee, P[r].u.y, a23);
        }
        a01 = add2(a01, __shfl_xor_sync(FULLMASK, a01, 4));
        a23 = add2(a23, __shfl_xor_sync(FULLMASK, a23, 4));

        // squared norm over 16 d (lane quad + xor1/xor2), with deferred inv
        u64 t2 = fma2(a23, a23, mul2(a01, a01));
        float2 th = unpk(t2);
        float sq_un = th.x + th.y;
        sq_un += __shfl_xor_sync(FULLMASK, sq_un, 1);
        sq_un += __shfl_xor_sync(FULLMASK, sq_un, 2);

        const float inv2 = inv * inv;
        const float sqe  = fmaf(sq_un, inv2, 1e-7f);   // true sq + eps
        const float f    = sqe * rsqf(sqe) * rcpf(1.0f + sqe) * inv;

        const u64 ff = bcast2(f);
        o01 = mul2(a01, ff);
        o23 = mul2(a23, ff);
        float2 u0 = unpk(o01), u1 = unpk(o23);
        o0 = u0.x; o1 = u0.y; o2 = u1.x; o3 = u1.y;
    };

    pass();
    for (int it = 0; it < iters; ++it) {
#pragma unroll
        for (int r = 0; r < 8; ++r) {
            float pa = P[r].f.x * o0 + P[r].f.y * o1 +
                       P[r].f.z * o2 + P[r].f.w * o3;
            pa += __shfl_xor_sync(FULLMASK, pa, 1);
            pa += __shfl_xor_sync(FULLMASK, pa, 2);
            bb[r] = fmaf(pa, LOG2E, bb[r]);   // log2-space update, free scale
        }
        pass();
    }

    if (h == 0) {
        ulonglong2 res; res.x = o01; res.y = o23;
        reinterpret_cast<ulonglong2*>(out)[(size_t)loc * 4 + q] = res;
    }
}

extern "C" void kernel_launch(void* const* d_in, const int* in_sizes, int n_in,
                              void* d_out, int out_size) {
    const float* pred = (const float*)d_in[0];
    const float* b    = (const float*)d_in[1];
    const int*   nit  = (const int*)d_in[2];
    float* out = (float*)d_out;

    const int n_loc = in_sizes[0] / 256;   // B*O*H*W
    const int ohw   = in_sizes[1] / 16;    // O*H*W

    const int warps  = (n_loc + 3) / 4;
    const int blocks = (warps + 7) / 8;
    routing_kernel<<<blocks, 256>>>(pred, b, nit, out, n_loc, ohw);
}